// round 12
// baseline (speedup 1.0000x reference)
#include <cuda_runtime.h>
#include <cuda_fp16.h>
#include <cstdint>

#define EMB 512
#define BATCH 8
#define SEQ 2048
#define TOK (BATCH * SEQ)   // 16384

// Scratch (allocation-free rule: __device__ globals)
__device__ __half g_Xh[(size_t)TOK * EMB];
__device__ __half g_QKV[(size_t)TOK * 3 * EMB];
__device__ __half g_Vt[(size_t)TOK * EMB];
__device__ __half g_O[(size_t)TOK * EMB];
__device__ __half g_S[(size_t)BATCH * SEQ * SEQ];
__device__ __half g_WT[4 * EMB * EMB];
__device__ float  g_Bqkv[3 * EMB];
__device__ float  g_Lpart[32 * TOK];
__device__ float  g_L[TOK];

// ---------------- PTX helpers (compute_103-safe) ----------------
__device__ __forceinline__ uint32_t smem_u32(const void* p) {
    uint32_t a;
    asm("{ .reg .u64 t; cvta.to.shared.u64 t, %1; cvt.u32.u64 %0, t; }" : "=r"(a) : "l"(p));
    return a;
}
__device__ __forceinline__ void cp16(uint32_t s, const void* g) {
    asm volatile("cp.async.cg.shared.global [%0], [%1], 16;" :: "r"(s), "l"(g));
}
#define CP_COMMIT() asm volatile("cp.async.commit_group;" ::: "memory")
#define CP_WAIT0()  asm volatile("cp.async.wait_group 0;" ::: "memory")
#define CP_WAIT1()  asm volatile("cp.async.wait_group 1;" ::: "memory")

#define LDSM4(r0, r1, r2, r3, addr)                                            \
    asm volatile("ldmatrix.sync.aligned.m8n8.x4.shared.b16 {%0,%1,%2,%3}, [%4];" \
        : "=r"(r0), "=r"(r1), "=r"(r2), "=r"(r3) : "r"(addr))

// FMA-pipe exp (no MUFU): x ~ [-16,16], rel err ~2e-6.
__device__ __forceinline__ float fexp(float x) {
    float t = x * 1.4426950408889634f;
    float r = rintf(t);
    float f = t - r;
    float p =          1.3333558146428443e-3f;
    p = fmaf(p, f,     9.6181291076284772e-3f);
    p = fmaf(p, f,     5.5504108664821580e-2f);
    p = fmaf(p, f,     2.4022650695910071e-1f);
    p = fmaf(p, f,     6.9314718055994531e-1f);
    p = fmaf(p, f,     1.0f);
    int i = (int)r;
    return p * __int_as_float((i + 127) << 23);
}

// fp16 MMA m16n8k16, fp32 accumulate.
__device__ __forceinline__ void mma_f16(float* d, const uint32_t* a, uint32_t b0, uint32_t b1) {
    asm volatile(
        "mma.sync.aligned.m16n8k16.row.col.f32.f16.f16.f32 "
        "{%0,%1,%2,%3}, {%4,%5,%6,%7}, {%8,%9}, {%0,%1,%2,%3};"
        : "+f"(d[0]), "+f"(d[1]), "+f"(d[2]), "+f"(d[3])
        : "r"(a[0]), "r"(a[1]), "r"(a[2]), "r"(a[3]), "r"(b0), "r"(b1));
}

// ---------------- NT fp16 GEMM (fp32 accum, ldmatrix, 64x64 warp tiles) -----
// C = scale * A @ B^T (+epilogue). A [M,lda], B [N,ldb] halves, K-major.
// Block tile 128x128, BK=64 halves, 4 warps (2x2), warp tile 64x64.
// 3-stage cp.async ring with wait_group 1 (fills run two tiles ahead),
// 2 CTAs/SM (2x110.6KB smem), stride-72 smem (conflict-free LDSM).
// EPI: 0 = +bias, ->half (QKV)   1 = exp, row-partial-sums, ->half (score)
//      2 = *invl[row], ->half (AV)   3 = +bias, ->float (final)
#define BK 64
#define STR 72
#define TILE_HALFS (128 * STR)               // 9216
#define STAGE_HALFS (2 * TILE_HALFS)         // 18432
#define STAGES 3
#define SMEM_BYTES (STAGES * STAGE_HALFS * 2)  // 110592

template <int EPI>
__global__ void __launch_bounds__(128, 2) gemm_nt(
    const __half* __restrict__ A, const __half* __restrict__ B,
    const float* __restrict__ aux, void* __restrict__ Cv,
    int lda, int ldb, int ldc, int K,
    size_t sA, size_t sB, size_t sC, int sAux, float scale)
{
    extern __shared__ __half smem[];
    const uint32_t sbase = smem_u32(smem);

    const int tid  = threadIdx.x;
    const int lane = tid & 31;
    const int warp = tid >> 5;
    const int wr = (warp & 1) * 64;   // warp row offset (2 row-warps)
    const int wc = (warp >> 1) * 64;  // warp col offset (2 col-warps)

    const int b = blockIdx.z;
    A += (size_t)b * sA;
    B += (size_t)b * sB;
    if (aux) aux += (size_t)b * sAux;
    const int row0 = blockIdx.y * 128;
    const int col0 = blockIdx.x * 128;

    float acc[4][8][4];
    #pragma unroll
    for (int mi = 0; mi < 4; mi++)
        #pragma unroll
        for (int ni = 0; ni < 8; ni++)
            #pragma unroll
            for (int j = 0; j < 4; j++) acc[mi][ni][j] = 0.0f;

    const __half* gA = A + (size_t)row0 * lda;
    const __half* gB = B + (size_t)col0 * ldb;

    auto fill = [&](int t, int buf) {
        uint32_t smA = sbase + (uint32_t)buf * STAGE_HALFS * 2;
        uint32_t smB = smA + TILE_HALFS * 2;
        const __half* pa = gA + t * BK;
        const __half* pb = gB + t * BK;
        const int frow0 = tid >> 3;      // 0..15
        const int cq    = tid & 7;       // 16B chunk in 128B row
        int row = frow0;
        #pragma unroll
        for (int it = 0; it < 8; it++, row += 16) {
            uint32_t off = 2u * (uint32_t)(row * STR + cq * 8);
            cp16(smA + off, pa + (size_t)row * lda + cq * 8);
            cp16(smB + off, pb + (size_t)row * ldb + cq * 8);
        }
    };

    const int ktiles = K / BK;
    fill(0, 0); CP_COMMIT();
    if (ktiles > 1) { fill(1, 1); CP_COMMIT(); }

    const int g = lane >> 2;
    const int q = lane & 3;
    const int l8 = lane & 7;
    const int jj = lane >> 3;    // which 8x8 matrix this lane addresses

    // ldmatrix per-lane byte offsets (kc=0), relative to tile base.
    // A matrices: j -> (row + 8*(j&1), k + 8*(j>>1))  => r0..r3 = a0..a3
    uint32_t aOff[4];
    #pragma unroll
    for (int mi = 0; mi < 4; mi++) {
        int row = wr + mi * 16 + (jj & 1) * 8 + l8;
        aOff[mi] = 2u * (uint32_t)(row * STR + (jj >> 1) * 8);
    }
    // B matrices: j -> (n + 8*(j>>1), k + 8*(j&1))  => (r0,r1)=b of ni; (r2,r3)=ni+1
    uint32_t bOff[4];
    #pragma unroll
    for (int p = 0; p < 4; p++) {
        int n = wc + p * 16 + (jj >> 1) * 8 + l8;
        bOff[p] = 2u * (uint32_t)(n * STR + (jj & 1) * 8);
    }

    for (int t = 0; t < ktiles; t++) {
        if (t == ktiles - 1) { CP_WAIT0(); }   // last fill must fully land
        else                 { CP_WAIT1(); }   // t resident; t+1 may fly
        __syncthreads();        // compute(t-1) done everywhere -> buf (t+2)%3 free
        if (t + 2 < ktiles) { fill(t + 2, (t + 2) % STAGES); CP_COMMIT(); }

        const uint32_t smA = sbase + (uint32_t)(t % STAGES) * STAGE_HALFS * 2;
        const uint32_t smB = smA + TILE_HALFS * 2;

        #pragma unroll
        for (int ks = 0; ks < 4; ks++) {      // 4 x k16
            const uint32_t kadd = (uint32_t)ks * 32;   // 16 halfs = 32B
            uint32_t a[4][4], bb[4][4];
            #pragma unroll
            for (int mi = 0; mi < 4; mi++)
                LDSM4(a[mi][0], a[mi][1], a[mi][2], a[mi][3], smA + aOff[mi] + kadd);
            #pragma unroll
            for (int p = 0; p < 4; p++)
                LDSM4(bb[p][0], bb[p][1], bb[p][2], bb[p][3], smB + bOff[p] + kadd);
            #pragma unroll
            for (int p = 0; p < 4; p++)
                #pragma unroll
                for (int mi = 0; mi < 4; mi++) {
                    mma_f16(acc[mi][2 * p],     a[mi], bb[p][0], bb[p][1]);
                    mma_f16(acc[mi][2 * p + 1], a[mi], bb[p][2], bb[p][3]);
                }
        }
    }

    // Epilogue
    float rs0[4], rs1[4];
    #pragma unroll
    for (int mi = 0; mi < 4; mi++) { rs0[mi] = 0.0f; rs1[mi] = 0.0f; }

    #pragma unroll
    for (int mi = 0; mi < 4; mi++) {
        int rloc = wr + mi * 16 + g;
        int r = row0 + rloc;
        float il0 = 1.0f, il1 = 1.0f;
        if (EPI == 2) { il0 = aux[r]; il1 = aux[r + 8]; }
        #pragma unroll
        for (int ni = 0; ni < 8; ni++) {
            int c = wc + ni * 8 + 2 * q;
            float2 v0, v1;
            v0.x = acc[mi][ni][0] * scale;
            v0.y = acc[mi][ni][1] * scale;
            v1.x = acc[mi][ni][2] * scale;
            v1.y = acc[mi][ni][3] * scale;
            if (EPI == 0 || EPI == 3) {
                float bx = aux[col0 + c], by = aux[col0 + c + 1];
                v0.x += bx; v0.y += by;
                v1.x += bx; v1.y += by;
            }
            if (EPI == 1) {
                v0.x = fexp(v0.x); v0.y = fexp(v0.y);
                v1.x = fexp(v1.x); v1.y = fexp(v1.y);
                rs0[mi] += v0.x + v0.y;
                rs1[mi] += v1.x + v1.y;
            }
            if (EPI == 2) {
                v0.x *= il0; v0.y *= il0;
                v1.x *= il1; v1.y *= il1;
            }
            if (EPI == 3) {
                float* c0 = (float*)Cv + (size_t)b * sC + (size_t)r * ldc + col0;
                float* c1 = c0 + (size_t)8 * ldc;
                *reinterpret_cast<float2*>(c0 + c) = v0;
                *reinterpret_cast<float2*>(c1 + c) = v1;
            } else {
                __half* c0 = (__half*)Cv + (size_t)b * sC + (size_t)r * ldc + col0;
                __half* c1 = c0 + (size_t)8 * ldc;
                *reinterpret_cast<__half2*>(c0 + c) = __floats2half2_rn(v0.x, v0.y);
                *reinterpret_cast<__half2*>(c1 + c) = __floats2half2_rn(v1.x, v1.y);
            }
        }
    }

    if (EPI == 1) {
        // reduce partial row sums across q (4 lanes per row), write Lpart.
        #pragma unroll
        for (int mi = 0; mi < 4; mi++) {
            rs0[mi] += __shfl_xor_sync(0xFFFFFFFF, rs0[mi], 1);
            rs0[mi] += __shfl_xor_sync(0xFFFFFFFF, rs0[mi], 2);
            rs1[mi] += __shfl_xor_sync(0xFFFFFFFF, rs1[mi], 1);
            rs1[mi] += __shfl_xor_sync(0xFFFFFFFF, rs1[mi], 2);
        }
        if (q == 0) {
            int slot = blockIdx.x * 2 + (warp >> 1);
            size_t base = (size_t)slot * TOK + (size_t)b * SEQ + row0 + wr;
            #pragma unroll
            for (int mi = 0; mi < 4; mi++) {
                g_Lpart[base + mi * 16 + g]     = rs0[mi];
                g_Lpart[base + mi * 16 + g + 8] = rs1[mi];
            }
        }
    }
}

// ---------------- row-sum finalize: invl[r] = 1 / sum_32 Lpart ----------------
__global__ void __launch_bounds__(256) rowsum_final(
    const float* __restrict__ LP, float* __restrict__ invl)
{
    int r = blockIdx.x * 256 + threadIdx.x;
    float s = 0.0f;
    #pragma unroll
    for (int i = 0; i < 32; i++) s += LP[(size_t)i * TOK + r];
    invl[r] = 1.0f / s;
}

// ---------------- fp32 -> fp16 copy ----------------
__global__ void __launch_bounds__(256) round_h(
    const float* __restrict__ in, __half* __restrict__ out)
{
    size_t i = ((size_t)blockIdx.x * 256 + threadIdx.x) * 8;
    float4 v0 = *reinterpret_cast<const float4*>(in + i);
    float4 v1 = *reinterpret_cast<const float4*>(in + i + 4);
    __half2 h[4];
    h[0] = __floats2half2_rn(v0.x, v0.y);
    h[1] = __floats2half2_rn(v0.z, v0.w);
    h[2] = __floats2half2_rn(v1.x, v1.y);
    h[3] = __floats2half2_rn(v1.z, v1.w);
    *reinterpret_cast<uint4*>(out + i) = *reinterpret_cast<uint4*>(h);
}

// ---------------- batched 512x512 weight transpose (fp32 -> fp16) ----------
__global__ void __launch_bounds__(256) transpose_w4(
    const float* __restrict__ w0, const float* __restrict__ w1,
    const float* __restrict__ w2, const float* __restrict__ w3,
    __half* __restrict__ out)
{
    __shared__ float t[32][33];
    const float* in = (blockIdx.z == 0) ? w0 : (blockIdx.z == 1) ? w1
                     : (blockIdx.z == 2) ? w2 : w3;
    out += (size_t)blockIdx.z * EMB * EMB;
    const int x = blockIdx.x * 32 + threadIdx.x;
    const int y0 = blockIdx.y * 32;
    #pragma unroll
    for (int j = threadIdx.y; j < 32; j += 8)
        t[j][threadIdx.x] = in[(size_t)(y0 + j) * EMB + x];
    __syncthreads();
    const int ox = blockIdx.y * 32 + threadIdx.x;
    const int oy0 = blockIdx.x * 32;
    #pragma unroll
    for (int j = threadIdx.y; j < 32; j += 8)
        out[(size_t)(oy0 + j) * EMB + ox] = __float2half_rn(t[threadIdx.x][j]);
}

__global__ void __launch_bounds__(256) transpose_h2h(
    const __half* __restrict__ in, __half* __restrict__ out,
    int ldIn, int ldOut, size_t sIn, size_t sOut)
{
    __shared__ __half t[32][34];
    in  += (size_t)blockIdx.z * sIn;
    out += (size_t)blockIdx.z * sOut;
    const int x = blockIdx.x * 32 + threadIdx.x;
    const int y0 = blockIdx.y * 32;
    #pragma unroll
    for (int j = threadIdx.y; j < 32; j += 8)
        t[j][threadIdx.x] = in[(size_t)(y0 + j) * ldIn + x];
    __syncthreads();
    const int ox = blockIdx.y * 32 + threadIdx.x;
    const int oy0 = blockIdx.x * 32;
    #pragma unroll
    for (int j = threadIdx.y; j < 32; j += 8)
        out[(size_t)(oy0 + j) * ldOut + ox] = t[threadIdx.x][j];
}

// ---------------- bias concat ----------------
__global__ void __launch_bounds__(256) concat_bias(
    const float* __restrict__ a, const float* __restrict__ b,
    const float* __restrict__ c, float* __restrict__ o)
{
    int i = blockIdx.x * 256 + threadIdx.x;   // 0..1535
    float v = (i < 512) ? a[i] : ((i < 1024) ? b[i - 512] : c[i - 1024]);
    o[i] = v;
}

// ---------------- host ----------------
extern "C" void kernel_launch(void* const* d_in, const int* in_sizes, int n_in,
                              void* d_out, int out_size)
{
    const float* x  = (const float*)d_in[0];
    const float* Wq = (const float*)d_in[1];
    const float* bq = (const float*)d_in[2];
    const float* Wk = (const float*)d_in[3];
    const float* bk = (const float*)d_in[4];
    const float* Wv = (const float*)d_in[5];
    const float* bv = (const float*)d_in[6];
    const float* Wo = (const float*)d_in[7];
    const float* bo = (const float*)d_in[8];
    float* out = (float*)d_out;

    __half *Xh, *QKV, *Vt, *S, *O, *WT;
    float *Bqkv, *LP, *L;
    cudaGetSymbolAddress((void**)&Xh,   g_Xh);
    cudaGetSymbolAddress((void**)&QKV,  g_QKV);
    cudaGetSymbolAddress((void**)&Vt,   g_Vt);
    cudaGetSymbolAddress((void**)&S,    g_S);
    cudaGetSymbolAddress((void**)&O,    g_O);
    cudaGetSymbolAddress((void**)&WT,   g_WT);
    cudaGetSymbolAddress((void**)&Bqkv, g_Bqkv);
    cudaGetSymbolAddress((void**)&LP,   g_Lpart);
    cudaGetSymbolAddress((void**)&L,    g_L);

    cudaFuncSetAttribute(gemm_nt<0>, cudaFuncAttributeMaxDynamicSharedMemorySize, SMEM_BYTES);
    cudaFuncSetAttribute(gemm_nt<1>, cudaFuncAttributeMaxDynamicSharedMemorySize, SMEM_BYTES);
    cudaFuncSetAttribute(gemm_nt<2>, cudaFuncAttributeMaxDynamicSharedMemorySize, SMEM_BYTES);
    cudaFuncSetAttribute(gemm_nt<3>, cudaFuncAttributeMaxDynamicSharedMemorySize, SMEM_BYTES);

    const float scale = 0.044194173824159216f;  // 1/sqrt(512)
    const size_t W2 = (size_t)EMB * EMB;

    // x -> fp16
    round_h<<<(TOK * EMB) / (256 * 8), 256>>>(x, Xh);

    // All 4 weight transposes in ONE launch (fp32 -> fp16).
    dim3 tb(32, 8);
    dim3 tgW4(EMB / 32, EMB / 32, 4);
    transpose_w4<<<tgW4, tb>>>(Wq, Wk, Wv, Wo, WT);
    concat_bias<<<6, 256>>>(bq, bk, bv, Bqkv);

    // Fused QKV projection: QKV[16384,1536] = Xh @ [Wq|Wk|Wv] + b -> fp16
    dim3 gqkv(3 * EMB / 128, TOK / 128, 1);
    gemm_nt<0><<<gqkv, 128, SMEM_BYTES>>>(
        Xh, WT, Bqkv, QKV, EMB, EMB, 3 * EMB, EMB, 0, 0, 0, 0, 1.0f);

    // V^T per batch: [EMB, SEQ] (V = QKV cols 1024..1535)
    dim3 tgV(EMB / 32, SEQ / 32, BATCH);
    transpose_h2h<<<tgV, tb>>>(QKV + 2 * EMB, Vt, 3 * EMB, SEQ,
                               (size_t)SEQ * 3 * EMB, (size_t)SEQ * EMB);

    // Scores + fused exp + row partial sums: S = exp(scale * Q @ K^T) -> fp16
    dim3 gscore(SEQ / 128, SEQ / 128, BATCH);
    gemm_nt<1><<<gscore, 128, SMEM_BYTES>>>(
        QKV, QKV + EMB, nullptr, S, 3 * EMB, 3 * EMB, SEQ, EMB,
        (size_t)SEQ * 3 * EMB, (size_t)SEQ * 3 * EMB, (size_t)SEQ * SEQ, 0, scale);

    // invl[r] = 1 / sum(exp row)
    rowsum_final<<<TOK / 256, 256>>>(LP, L);

    // O[b] = (S[b] @ V[b]) * invl[row] -> fp16
    dim3 gav(EMB / 128, SEQ / 128, BATCH);
    gemm_nt<2><<<gav, 128, SMEM_BYTES>>>(
        S, Vt, L, O, SEQ, SEQ, EMB, SEQ,
        (size_t)SEQ * SEQ, (size_t)SEQ * EMB, (size_t)SEQ * EMB, SEQ, 1.0f);

    // Final projection: out = O @ Wo + bo (fp32 out)
    dim3 gout(EMB / 128, TOK / 128, 1);
    gemm_nt<3><<<gout, 128, SMEM_BYTES>>>(
        O, WT + 3 * W2, bo, out, EMB, EMB, EMB, EMB, 0, 0, 0, 0, 1.0f);
}

// round 13
// speedup vs baseline: 1.0035x; 1.0035x over previous
#include <cuda_runtime.h>
#include <cuda_fp16.h>
#include <cstdint>

#define EMB 512
#define BATCH 8
#define SEQ 2048
#define TOK (BATCH * SEQ)   // 16384

// Scratch (allocation-free rule: __device__ globals)
__device__ __half g_Xh[(size_t)TOK * EMB];
__device__ __half g_QKV[(size_t)TOK * 3 * EMB];
__device__ __half g_Vt[(size_t)TOK * EMB];
__device__ __half g_O[(size_t)TOK * EMB];
__device__ __half g_S[(size_t)BATCH * SEQ * SEQ];
__device__ __half g_WT[4 * EMB * EMB];
__device__ float  g_Bqkv[3 * EMB];
__device__ float  g_Lpart[32 * TOK];
__device__ float  g_L[TOK];

// ---------------- PTX helpers (compute_103-safe) ----------------
__device__ __forceinline__ uint32_t smem_u32(const void* p) {
    uint32_t a;
    asm("{ .reg .u64 t; cvta.to.shared.u64 t, %1; cvt.u32.u64 %0, t; }" : "=r"(a) : "l"(p));
    return a;
}
__device__ __forceinline__ void cp16(uint32_t s, const void* g) {
    asm volatile("cp.async.cg.shared.global [%0], [%1], 16;" :: "r"(s), "l"(g));
}
#define CP_COMMIT() asm volatile("cp.async.commit_group;" ::: "memory")
#define CP_WAIT0()  asm volatile("cp.async.wait_group 0;" ::: "memory")

#define LDSM4(r0, r1, r2, r3, addr)                                            \
    asm volatile("ldmatrix.sync.aligned.m8n8.x4.shared.b16 {%0,%1,%2,%3}, [%4];" \
        : "=r"(r0), "=r"(r1), "=r"(r2), "=r"(r3) : "r"(addr))

// FMA-pipe exp (no MUFU): x ~ [-16,16], rel err ~2e-6.
__device__ __forceinline__ float fexp(float x) {
    float t = x * 1.4426950408889634f;
    float r = rintf(t);
    float f = t - r;
    float p =          1.3333558146428443e-3f;
    p = fmaf(p, f,     9.6181291076284772e-3f);
    p = fmaf(p, f,     5.5504108664821580e-2f);
    p = fmaf(p, f,     2.4022650695910071e-1f);
    p = fmaf(p, f,     6.9314718055994531e-1f);
    p = fmaf(p, f,     1.0f);
    int i = (int)r;
    return p * __int_as_float((i + 127) << 23);
}

// fp16 MMA m16n8k16, fp32 accumulate.
__device__ __forceinline__ void mma_f16(float* d, const uint32_t* a, uint32_t b0, uint32_t b1) {
    asm volatile(
        "mma.sync.aligned.m16n8k16.row.col.f32.f16.f16.f32 "
        "{%0,%1,%2,%3}, {%4,%5,%6,%7}, {%8,%9}, {%0,%1,%2,%3};"
        : "+f"(d[0]), "+f"(d[1]), "+f"(d[2]), "+f"(d[3])
        : "r"(a[0]), "r"(a[1]), "r"(a[2]), "r"(a[3]), "r"(b0), "r"(b1));
}

// ------- Persistent NT fp16 GEMM (fp32 accum, ldmatrix, 64x64 warp tiles) ----
// C = scale * A @ B^T (+epilogue). A [M,lda], B [N,ldb] halves, K-major.
// Block tile 128x128, BK=64 halves, 4 warps (2x2), 2-stage cp.async,
// 2 CTAs/SM, stride-72 smem. PERSISTENT: grid = min(numTiles, 296); each CTA
// loops tiles with stride gridDim.x (kills wave quantization). Next tile's
// stage-0 fill is prefetched during the current tile's last k-iteration
// (ktiles even -> buffer parity preserved; buf0 free after the t=ktiles-1
// barrier; epilogue touches no smem).
// EPI: 0 = +bias, ->half (QKV)   1 = exp, row-partial-sums, ->half (score)
//      2 = *invl[row], ->half (AV)   3 = +bias, ->float (final)
#define BK 64
#define STR 72
#define TILE_HALFS (128 * STR)               // 9216
#define STAGE_HALFS (2 * TILE_HALFS)         // 18432
#define SMEM_BYTES (2 * STAGE_HALFS * 2)     // 73728

template <int EPI>
__global__ void __launch_bounds__(128, 2) gemm_nt(
    const __half* __restrict__ A, const __half* __restrict__ B,
    const float* __restrict__ aux, void* __restrict__ Cv,
    int lda, int ldb, int ldc, int K,
    size_t sA, size_t sB, size_t sC, int sAux, float scale,
    int gx, int gxy, int numTiles)
{
    extern __shared__ __half smem[];
    const uint32_t sbase = smem_u32(smem);

    const int tid  = threadIdx.x;
    const int lane = tid & 31;
    const int warp = tid >> 5;
    const int wr = (warp & 1) * 64;   // warp row offset (2 row-warps)
    const int wc = (warp >> 1) * 64;  // warp col offset (2 col-warps)
    const int ktiles = K / BK;        // always even here

    const int g = lane >> 2;
    const int q = lane & 3;
    const int l8 = lane & 7;
    const int jj = lane >> 3;

    // ldmatrix per-lane byte offsets (tile-base relative); same as R11.
    uint32_t aOff[4];
    #pragma unroll
    for (int mi = 0; mi < 4; mi++) {
        int row = wr + mi * 16 + (jj & 1) * 8 + l8;
        aOff[mi] = 2u * (uint32_t)(row * STR + (jj >> 1) * 8);
    }
    uint32_t bOff[4];
    #pragma unroll
    for (int p = 0; p < 4; p++) {
        int n = wc + p * 16 + (jj >> 1) * 8 + l8;
        bOff[p] = 2u * (uint32_t)(n * STR + (jj & 1) * 8);
    }

    // fill one stage buffer from given tile-local pointers (at k-offset built in)
    auto fillp = [&](const __half* pa, const __half* pb, uint32_t buf) {
        uint32_t smA = sbase + buf * STAGE_HALFS * 2;
        uint32_t smB = smA + TILE_HALFS * 2;
        const int frow0 = tid >> 3;
        const int cq    = tid & 7;
        int row = frow0;
        #pragma unroll
        for (int it = 0; it < 8; it++, row += 16) {
            uint32_t off = 2u * (uint32_t)(row * STR + cq * 8);
            cp16(smA + off, pa + (size_t)row * lda + cq * 8);
            cp16(smB + off, pb + (size_t)row * ldb + cq * 8);
        }
    };

    int tile = blockIdx.x;
    if (tile >= numTiles) return;

    // decode tile -> (bx, by, bz)
    int bz = tile / gxy;
    int rem = tile - bz * gxy;
    int by = rem / gx;
    int bx = rem - by * gx;
    const __half* tA = A + (size_t)bz * sA + (size_t)(by * 128) * lda;
    const __half* tB = B + (size_t)bz * sB + (size_t)(bx * 128) * ldb;

    // prologue: first tile's two stages
    fillp(tA, tB, 0); CP_COMMIT();
    fillp(tA + BK, tB + BK, 1); CP_COMMIT();

    for (;;) {
        float acc[4][8][4];
        #pragma unroll
        for (int mi = 0; mi < 4; mi++)
            #pragma unroll
            for (int ni = 0; ni < 8; ni++)
                #pragma unroll
                for (int j = 0; j < 4; j++) acc[mi][ni][j] = 0.0f;

        for (int t = 0; t < ktiles; t++) {
            CP_WAIT0();             // stage t resident
            __syncthreads();        // all warps done with t-1 -> its buffer free
            if (t + 1 < ktiles) {
                fillp(tA + (t + 1) * BK, tB + (t + 1) * BK, (t + 1) & 1);
            } else {
                int nt = tile + gridDim.x;     // prefetch next tile stage 0 (buf0)
                if (nt < numTiles) {
                    int nbz = nt / gxy;
                    int nrem = nt - nbz * gxy;
                    int nby = nrem / gx;
                    int nbx = nrem - nby * gx;
                    fillp(A + (size_t)nbz * sA + (size_t)(nby * 128) * lda,
                          B + (size_t)nbz * sB + (size_t)(nbx * 128) * ldb, 0);
                }
            }
            CP_COMMIT();

            const uint32_t smA = sbase + (uint32_t)(t & 1) * STAGE_HALFS * 2;
            const uint32_t smB = smA + TILE_HALFS * 2;

            #pragma unroll
            for (int ks = 0; ks < 4; ks++) {      // 4 x k16
                const uint32_t kadd = (uint32_t)ks * 32;
                uint32_t a[4][4], bb[4][4];
                #pragma unroll
                for (int mi = 0; mi < 4; mi++)
                    LDSM4(a[mi][0], a[mi][1], a[mi][2], a[mi][3], smA + aOff[mi] + kadd);
                #pragma unroll
                for (int p = 0; p < 4; p++)
                    LDSM4(bb[p][0], bb[p][1], bb[p][2], bb[p][3], smB + bOff[p] + kadd);
                #pragma unroll
                for (int p = 0; p < 4; p++)
                    #pragma unroll
                    for (int mi = 0; mi < 4; mi++) {
                        mma_f16(acc[mi][2 * p],     a[mi], bb[p][0], bb[p][1]);
                        mma_f16(acc[mi][2 * p + 1], a[mi], bb[p][2], bb[p][3]);
                    }
            }
        }

        // -------- epilogue (no smem) --------
        const int row0 = by * 128;
        const int col0 = bx * 128;
        const float* auxb = aux;
        if (EPI == 2) auxb = aux + (size_t)bz * sAux;

        float rs0[4], rs1[4];
        #pragma unroll
        for (int mi = 0; mi < 4; mi++) { rs0[mi] = 0.0f; rs1[mi] = 0.0f; }

        #pragma unroll
        for (int mi = 0; mi < 4; mi++) {
            int rloc = wr + mi * 16 + g;
            int r = row0 + rloc;
            float il0 = 1.0f, il1 = 1.0f;
            if (EPI == 2) { il0 = auxb[r]; il1 = auxb[r + 8]; }
            #pragma unroll
            for (int ni = 0; ni < 8; ni++) {
                int c = wc + ni * 8 + 2 * q;
                float2 v0, v1;
                v0.x = acc[mi][ni][0] * scale;
                v0.y = acc[mi][ni][1] * scale;
                v1.x = acc[mi][ni][2] * scale;
                v1.y = acc[mi][ni][3] * scale;
                if (EPI == 0 || EPI == 3) {
                    float bxs = auxb[col0 + c], bys = auxb[col0 + c + 1];
                    v0.x += bxs; v0.y += bys;
                    v1.x += bxs; v1.y += bys;
                }
                if (EPI == 1) {
                    v0.x = fexp(v0.x); v0.y = fexp(v0.y);
                    v1.x = fexp(v1.x); v1.y = fexp(v1.y);
                    rs0[mi] += v0.x + v0.y;
                    rs1[mi] += v1.x + v1.y;
                }
                if (EPI == 2) {
                    v0.x *= il0; v0.y *= il0;
                    v1.x *= il1; v1.y *= il1;
                }
                if (EPI == 3) {
                    float* c0 = (float*)Cv + (size_t)bz * sC + (size_t)r * ldc + col0;
                    float* c1 = c0 + (size_t)8 * ldc;
                    *reinterpret_cast<float2*>(c0 + c) = v0;
                    *reinterpret_cast<float2*>(c1 + c) = v1;
                } else {
                    __half* c0 = (__half*)Cv + (size_t)bz * sC + (size_t)r * ldc + col0;
                    __half* c1 = c0 + (size_t)8 * ldc;
                    *reinterpret_cast<__half2*>(c0 + c) = __floats2half2_rn(v0.x, v0.y);
                    *reinterpret_cast<__half2*>(c1 + c) = __floats2half2_rn(v1.x, v1.y);
                }
            }
        }

        if (EPI == 1) {
            #pragma unroll
            for (int mi = 0; mi < 4; mi++) {
                rs0[mi] += __shfl_xor_sync(0xFFFFFFFF, rs0[mi], 1);
                rs0[mi] += __shfl_xor_sync(0xFFFFFFFF, rs0[mi], 2);
                rs1[mi] += __shfl_xor_sync(0xFFFFFFFF, rs1[mi], 1);
                rs1[mi] += __shfl_xor_sync(0xFFFFFFFF, rs1[mi], 2);
            }
            if (q == 0) {
                int slot = bx * 2 + (warp >> 1);
                size_t base = (size_t)slot * TOK + (size_t)bz * SEQ + row0 + wr;
                #pragma unroll
                for (int mi = 0; mi < 4; mi++) {
                    g_Lpart[base + mi * 16 + g]     = rs0[mi];
                    g_Lpart[base + mi * 16 + g + 8] = rs1[mi];
                }
            }
        }

        // -------- advance to next tile --------
        tile += gridDim.x;
        if (tile >= numTiles) break;
        bz = tile / gxy;
        rem = tile - bz * gxy;
        by = rem / gx;
        bx = rem - by * gx;
        tA = A + (size_t)bz * sA + (size_t)(by * 128) * lda;
        tB = B + (size_t)bz * sB + (size_t)(bx * 128) * ldb;
        // stage 0 of this tile already in flight; stage 1 fills at t=0.
        // (t=0 iteration will fill buf1 after its barrier — buf1's last use
        //  was the previous tile's final compute, finished by then.)
        // Note: t=0 fill below uses (t+1)&1 = 1. Stage-1 data waits one iter.
        // To keep WAIT0 semantics exact, fill stage1 now is NOT safe (buf1
        // may still be read by laggard warps) — handled by the in-loop path.
    }
}

// ---------------- row-sum finalize: invl[r] = 1 / sum_32 Lpart ----------------
__global__ void __launch_bounds__(256) rowsum_final(
    const float* __restrict__ LP, float* __restrict__ invl)
{
    int r = blockIdx.x * 256 + threadIdx.x;
    float s = 0.0f;
    #pragma unroll
    for (int i = 0; i < 32; i++) s += LP[(size_t)i * TOK + r];
    invl[r] = 1.0f / s;
}

// ---------------- fp32 -> fp16 copy ----------------
__global__ void __launch_bounds__(256) round_h(
    const float* __restrict__ in, __half* __restrict__ out)
{
    size_t i = ((size_t)blockIdx.x * 256 + threadIdx.x) * 8;
    float4 v0 = *reinterpret_cast<const float4*>(in + i);
    float4 v1 = *reinterpret_cast<const float4*>(in + i + 4);
    __half2 h[4];
    h[0] = __floats2half2_rn(v0.x, v0.y);
    h[1] = __floats2half2_rn(v0.z, v0.w);
    h[2] = __floats2half2_rn(v1.x, v1.y);
    h[3] = __floats2half2_rn(v1.z, v1.w);
    *reinterpret_cast<uint4*>(out + i) = *reinterpret_cast<uint4*>(h);
}

// ---------------- batched 512x512 weight transpose (fp32 -> fp16) ----------
__global__ void __launch_bounds__(256) transpose_w4(
    const float* __restrict__ w0, const float* __restrict__ w1,
    const float* __restrict__ w2, const float* __restrict__ w3,
    __half* __restrict__ out)
{
    __shared__ float t[32][33];
    const float* in = (blockIdx.z == 0) ? w0 : (blockIdx.z == 1) ? w1
                     : (blockIdx.z == 2) ? w2 : w3;
    out += (size_t)blockIdx.z * EMB * EMB;
    const int x = blockIdx.x * 32 + threadIdx.x;
    const int y0 = blockIdx.y * 32;
    #pragma unroll
    for (int j = threadIdx.y; j < 32; j += 8)
        t[j][threadIdx.x] = in[(size_t)(y0 + j) * EMB + x];
    __syncthreads();
    const int ox = blockIdx.y * 32 + threadIdx.x;
    const int oy0 = blockIdx.x * 32;
    #pragma unroll
    for (int j = threadIdx.y; j < 32; j += 8)
        out[(size_t)(oy0 + j) * EMB + ox] = __float2half_rn(t[threadIdx.x][j]);
}

__global__ void __launch_bounds__(256) transpose_h2h(
    const __half* __restrict__ in, __half* __restrict__ out,
    int ldIn, int ldOut, size_t sIn, size_t sOut)
{
    __shared__ __half t[32][34];
    in  += (size_t)blockIdx.z * sIn;
    out += (size_t)blockIdx.z * sOut;
    const int x = blockIdx.x * 32 + threadIdx.x;
    const int y0 = blockIdx.y * 32;
    #pragma unroll
    for (int j = threadIdx.y; j < 32; j += 8)
        t[j][threadIdx.x] = in[(size_t)(y0 + j) * ldIn + x];
    __syncthreads();
    const int ox = blockIdx.y * 32 + threadIdx.x;
    const int oy0 = blockIdx.x * 32;
    #pragma unroll
    for (int j = threadIdx.y; j < 32; j += 8)
        out[(size_t)(oy0 + j) * ldOut + ox] = t[threadIdx.x][j];
}

// ---------------- bias concat ----------------
__global__ void __launch_bounds__(256) concat_bias(
    const float* __restrict__ a, const float* __restrict__ b,
    const float* __restrict__ c, float* __restrict__ o)
{
    int i = blockIdx.x * 256 + threadIdx.x;   // 0..1535
    float v = (i < 512) ? a[i] : ((i < 1024) ? b[i - 512] : c[i - 1024]);
    o[i] = v;
}

// ---------------- host ----------------
extern "C" void kernel_launch(void* const* d_in, const int* in_sizes, int n_in,
                              void* d_out, int out_size)
{
    const float* x  = (const float*)d_in[0];
    const float* Wq = (const float*)d_in[1];
    const float* bq = (const float*)d_in[2];
    const float* Wk = (const float*)d_in[3];
    const float* bk = (const float*)d_in[4];
    const float* Wv = (const float*)d_in[5];
    const float* bv = (const float*)d_in[6];
    const float* Wo = (const float*)d_in[7];
    const float* bo = (const float*)d_in[8];
    float* out = (float*)d_out;

    __half *Xh, *QKV, *Vt, *S, *O, *WT;
    float *Bqkv, *LP, *L;
    cudaGetSymbolAddress((void**)&Xh,   g_Xh);
    cudaGetSymbolAddress((void**)&QKV,  g_QKV);
    cudaGetSymbolAddress((void**)&Vt,   g_Vt);
    cudaGetSymbolAddress((void**)&S,    g_S);
    cudaGetSymbolAddress((void**)&O,    g_O);
    cudaGetSymbolAddress((void**)&WT,   g_WT);
    cudaGetSymbolAddress((void**)&Bqkv, g_Bqkv);
    cudaGetSymbolAddress((void**)&LP,   g_Lpart);
    cudaGetSymbolAddress((void**)&L,    g_L);

    cudaFuncSetAttribute(gemm_nt<0>, cudaFuncAttributeMaxDynamicSharedMemorySize, SMEM_BYTES);
    cudaFuncSetAttribute(gemm_nt<1>, cudaFuncAttributeMaxDynamicSharedMemorySize, SMEM_BYTES);
    cudaFuncSetAttribute(gemm_nt<2>, cudaFuncAttributeMaxDynamicSharedMemorySize, SMEM_BYTES);
    cudaFuncSetAttribute(gemm_nt<3>, cudaFuncAttributeMaxDynamicSharedMemorySize, SMEM_BYTES);

    const float scale = 0.044194173824159216f;  // 1/sqrt(512)
    const size_t W2 = (size_t)EMB * EMB;
    const int PERSIST = 296;   // 148 SMs x 2 CTAs

    // x -> fp16
    round_h<<<(TOK * EMB) / (256 * 8), 256>>>(x, Xh);

    // All 4 weight transposes in ONE launch (fp32 -> fp16).
    dim3 tb(32, 8);
    dim3 tgW4(EMB / 32, EMB / 32, 4);
    transpose_w4<<<tgW4, tb>>>(Wq, Wk, Wv, Wo, WT);
    concat_bias<<<6, 256>>>(bq, bk, bv, Bqkv);

    // Fused QKV projection: 12 x 128 tiles = 1536
    {
        int gx = 12, gy = 128, nt = gx * gy;
        gemm_nt<0><<<PERSIST, 128, SMEM_BYTES>>>(
            Xh, WT, Bqkv, QKV, EMB, EMB, 3 * EMB, EMB,
            0, 0, 0, 0, 1.0f, gx, gx * gy, nt);
    }

    // V^T per batch: [EMB, SEQ] (V = QKV cols 1024..1535)
    dim3 tgV(EMB / 32, SEQ / 32, BATCH);
    transpose_h2h<<<tgV, tb>>>(QKV + 2 * EMB, Vt, 3 * EMB, SEQ,
                               (size_t)SEQ * 3 * EMB, (size_t)SEQ * EMB);

    // Scores + fused exp + row partial sums: 16 x 16 x 8 = 2048 tiles
    {
        int gx = 16, gy = 16, nt = gx * gy * BATCH;
        gemm_nt<1><<<PERSIST, 128, SMEM_BYTES>>>(
            QKV, QKV + EMB, nullptr, S, 3 * EMB, 3 * EMB, SEQ, EMB,
            (size_t)SEQ * 3 * EMB, (size_t)SEQ * 3 * EMB, (size_t)SEQ * SEQ,
            0, scale, gx, gx * gy, nt);
    }

    // invl[r] = 1 / sum(exp row)
    rowsum_final<<<TOK / 256, 256>>>(LP, L);

    // O[b] = (S[b] @ V[b]) * invl[row]: 4 x 16 x 8 = 512 tiles
    {
        int gx = 4, gy = 16, nt = gx * gy * BATCH;
        gemm_nt<2><<<PERSIST, 128, SMEM_BYTES>>>(
            S, Vt, L, O, SEQ, SEQ, EMB, SEQ,
            (size_t)SEQ * SEQ, (size_t)SEQ * EMB, (size_t)SEQ * EMB,
            SEQ, 1.0f, gx, gx * gy, nt);
    }

    // Final projection: 4 x 128 = 512 tiles (fp32 out)
    {
        int gx = 4, gy = 128, nt = gx * gy;
        gemm_nt<3><<<PERSIST, 128, SMEM_BYTES>>>(
            O, WT + 3 * W2, bo, out, EMB, EMB, EMB, EMB,
            0, 0, 0, 0, 1.0f, gx, gx * gy, nt);
    }
}

// round 14
// speedup vs baseline: 1.0055x; 1.0020x over previous
#include <cuda_runtime.h>
#include <cuda_fp16.h>
#include <cstdint>

#define EMB 512
#define BATCH 8
#define SEQ 2048
#define TOK (BATCH * SEQ)   // 16384

// Scratch (allocation-free rule: __device__ globals)
__device__ __half g_Xh[(size_t)TOK * EMB];
__device__ __half g_QKV[(size_t)TOK * 3 * EMB];
__device__ __half g_Vt[(size_t)TOK * EMB];
__device__ __half g_O[(size_t)TOK * EMB];
__device__ __half g_S[(size_t)BATCH * SEQ * SEQ];
__device__ __half g_WT[4 * EMB * EMB];
__device__ float  g_Bqkv[3 * EMB];
__device__ float  g_Lpart[32 * TOK];
__device__ float  g_L[TOK];

// ---------------- PTX helpers (compute_103-safe) ----------------
__device__ __forceinline__ uint32_t smem_u32(const void* p) {
    uint32_t a;
    asm("{ .reg .u64 t; cvta.to.shared.u64 t, %1; cvt.u32.u64 %0, t; }" : "=r"(a) : "l"(p));
    return a;
}
__device__ __forceinline__ void cp16(uint32_t s, const void* g) {
    asm volatile("cp.async.cg.shared.global [%0], [%1], 16;" :: "r"(s), "l"(g));
}
#define CP_COMMIT() asm volatile("cp.async.commit_group;" ::: "memory")
#define CP_WAIT0()  asm volatile("cp.async.wait_group 0;" ::: "memory")

#define LDSM4(r0, r1, r2, r3, addr)                                            \
    asm volatile("ldmatrix.sync.aligned.m8n8.x4.shared.b16 {%0,%1,%2,%3}, [%4];" \
        : "=r"(r0), "=r"(r1), "=r"(r2), "=r"(r3) : "r"(addr))

// FMA-pipe exp (no MUFU): x ~ [-16,16], rel err ~2e-6.
__device__ __forceinline__ float fexp(float x) {
    float t = x * 1.4426950408889634f;
    float r = rintf(t);
    float f = t - r;
    float p =          1.3333558146428443e-3f;
    p = fmaf(p, f,     9.6181291076284772e-3f);
    p = fmaf(p, f,     5.5504108664821580e-2f);
    p = fmaf(p, f,     2.4022650695910071e-1f);
    p = fmaf(p, f,     6.9314718055994531e-1f);
    p = fmaf(p, f,     1.0f);
    int i = (int)r;
    return p * __int_as_float((i + 127) << 23);
}

// fp16 MMA m16n8k16, fp32 accumulate.
__device__ __forceinline__ void mma_f16(float* d, const uint32_t* a, uint32_t b0, uint32_t b1) {
    asm volatile(
        "mma.sync.aligned.m16n8k16.row.col.f32.f16.f16.f32 "
        "{%0,%1,%2,%3}, {%4,%5,%6,%7}, {%8,%9}, {%0,%1,%2,%3};"
        : "+f"(d[0]), "+f"(d[1]), "+f"(d[2]), "+f"(d[3])
        : "r"(a[0]), "r"(a[1]), "r"(a[2]), "r"(a[3]), "r"(b0), "r"(b1));
}

// fp16 MMA m16n8k16, fp16 accumulate (2 packed-b32 acc regs).
__device__ __forceinline__ void mma_f16h(uint32_t* d, const uint32_t* a, uint32_t b0, uint32_t b1) {
    asm volatile(
        "mma.sync.aligned.m16n8k16.row.col.f16.f16.f16.f16 "
        "{%0,%1}, {%2,%3,%4,%5}, {%6,%7}, {%0,%1};"
        : "+r"(d[0]), "+r"(d[1])
        : "r"(a[0]), "r"(a[1]), "r"(a[2]), "r"(a[3]), "r"(b0), "r"(b1));
}

// ---------------- NT fp16 GEMM (ldmatrix, 64x64 warp tiles) ----------------
// C = scale * A @ B^T (+epilogue). A [M,lda], B [N,ldb] halves, K-major.
// Block tile 128x128, BK=64 halves, 4 warps (2x2), 2-stage cp.async,
// 2 CTAs/SM, stride-72 smem (conflict-free LDSM).
// EPI: 0 = +bias, x scale on cols<512 (Q pre-scale), ->half (QKV)
//      1 = fp16-ACCUM mma, exp, row-partial-sums, ->half (score)
//      2 = *invl[row], ->half (AV)   3 = +bias, ->float (final)
#define BK 64
#define STR 72
#define TILE_HALFS (128 * STR)               // 9216
#define STAGE_HALFS (2 * TILE_HALFS)         // 18432
#define SMEM_BYTES (2 * STAGE_HALFS * 2)     // 73728

template <int EPI>
__global__ void __launch_bounds__(128, 2) gemm_nt(
    const __half* __restrict__ A, const __half* __restrict__ B,
    const float* __restrict__ aux, void* __restrict__ Cv,
    int lda, int ldb, int ldc, int K,
    size_t sA, size_t sB, size_t sC, int sAux, float scale)
{
    extern __shared__ __half smem[];
    const uint32_t sbase = smem_u32(smem);

    const int tid  = threadIdx.x;
    const int lane = tid & 31;
    const int warp = tid >> 5;
    const int wr = (warp & 1) * 64;
    const int wc = (warp >> 1) * 64;

    const int b = blockIdx.z;
    A += (size_t)b * sA;
    B += (size_t)b * sB;
    if (aux) aux += (size_t)b * sAux;
    const int row0 = blockIdx.y * 128;
    const int col0 = blockIdx.x * 128;

    // fp32 accumulators (EPI != 1) or fp16 accumulators (EPI == 1)
    float    acc[4][8][4];
    uint32_t hac[4][8][2];
    if (EPI == 1) {
        #pragma unroll
        for (int mi = 0; mi < 4; mi++)
            #pragma unroll
            for (int ni = 0; ni < 8; ni++) { hac[mi][ni][0] = 0u; hac[mi][ni][1] = 0u; }
    } else {
        #pragma unroll
        for (int mi = 0; mi < 4; mi++)
            #pragma unroll
            for (int ni = 0; ni < 8; ni++)
                #pragma unroll
                for (int j = 0; j < 4; j++) acc[mi][ni][j] = 0.0f;
    }

    const __half* gA = A + (size_t)row0 * lda;
    const __half* gB = B + (size_t)col0 * ldb;

    auto fill = [&](int t, int buf) {
        uint32_t smA = sbase + (uint32_t)buf * STAGE_HALFS * 2;
        uint32_t smB = smA + TILE_HALFS * 2;
        const __half* pa = gA + t * BK;
        const __half* pb = gB + t * BK;
        const int frow0 = tid >> 3;
        const int cq    = tid & 7;
        int row = frow0;
        #pragma unroll
        for (int it = 0; it < 8; it++, row += 16) {
            uint32_t off = 2u * (uint32_t)(row * STR + cq * 8);
            cp16(smA + off, pa + (size_t)row * lda + cq * 8);
            cp16(smB + off, pb + (size_t)row * ldb + cq * 8);
        }
    };

    const int ktiles = K / BK;
    fill(0, 0); CP_COMMIT();

    const int g = lane >> 2;
    const int q = lane & 3;
    const int l8 = lane & 7;
    const int jj = lane >> 3;

    uint32_t aOff[4];
    #pragma unroll
    for (int mi = 0; mi < 4; mi++) {
        int row = wr + mi * 16 + (jj & 1) * 8 + l8;
        aOff[mi] = 2u * (uint32_t)(row * STR + (jj >> 1) * 8);
    }
    uint32_t bOff[4];
    #pragma unroll
    for (int p = 0; p < 4; p++) {
        int n = wc + p * 16 + (jj >> 1) * 8 + l8;
        bOff[p] = 2u * (uint32_t)(n * STR + (jj & 1) * 8);
    }

    for (int t = 0; t < ktiles; t++) {
        CP_WAIT0();
        __syncthreads();
        if (t + 1 < ktiles) { fill(t + 1, (t + 1) & 1); CP_COMMIT(); }

        const uint32_t smA = sbase + (uint32_t)(t & 1) * STAGE_HALFS * 2;
        const uint32_t smB = smA + TILE_HALFS * 2;

        #pragma unroll
        for (int ks = 0; ks < 4; ks++) {
            const uint32_t kadd = (uint32_t)ks * 32;
            uint32_t a[4][4], bb[4][4];
            #pragma unroll
            for (int mi = 0; mi < 4; mi++)
                LDSM4(a[mi][0], a[mi][1], a[mi][2], a[mi][3], smA + aOff[mi] + kadd);
            #pragma unroll
            for (int p = 0; p < 4; p++)
                LDSM4(bb[p][0], bb[p][1], bb[p][2], bb[p][3], smB + bOff[p] + kadd);
            #pragma unroll
            for (int p = 0; p < 4; p++)
                #pragma unroll
                for (int mi = 0; mi < 4; mi++) {
                    if (EPI == 1) {
                        mma_f16h(hac[mi][2 * p],     a[mi], bb[p][0], bb[p][1]);
                        mma_f16h(hac[mi][2 * p + 1], a[mi], bb[p][2], bb[p][3]);
                    } else {
                        mma_f16(acc[mi][2 * p],     a[mi], bb[p][0], bb[p][1]);
                        mma_f16(acc[mi][2 * p + 1], a[mi], bb[p][2], bb[p][3]);
                    }
                }
        }
    }

    // Epilogue
    float rs0[4], rs1[4];
    #pragma unroll
    for (int mi = 0; mi < 4; mi++) { rs0[mi] = 0.0f; rs1[mi] = 0.0f; }

    #pragma unroll
    for (int mi = 0; mi < 4; mi++) {
        int rloc = wr + mi * 16 + g;
        int r = row0 + rloc;
        float il0 = 1.0f, il1 = 1.0f;
        if (EPI == 2) { il0 = aux[r]; il1 = aux[r + 8]; }
        #pragma unroll
        for (int ni = 0; ni < 8; ni++) {
            int c = wc + ni * 8 + 2 * q;
            float2 v0, v1;
            if (EPI == 1) {
                __half2 h0 = *reinterpret_cast<__half2*>(&hac[mi][ni][0]);
                __half2 h1 = *reinterpret_cast<__half2*>(&hac[mi][ni][1]);
                v0.x = __low2float(h0); v0.y = __high2float(h0);
                v1.x = __low2float(h1); v1.y = __high2float(h1);
            } else {
                v0.x = acc[mi][ni][0] * scale;
                v0.y = acc[mi][ni][1] * scale;
                v1.x = acc[mi][ni][2] * scale;
                v1.y = acc[mi][ni][3] * scale;
            }
            if (EPI == 0 || EPI == 3) {
                float bx = aux[col0 + c], by = aux[col0 + c + 1];
                v0.x += bx; v0.y += by;
                v1.x += bx; v1.y += by;
            }
            if (EPI == 0 && col0 < 512) {
                // Q columns: fold in 1/sqrt(d) so the score GEMM needs no scale
                // (enables fp16 accumulation at ~0.33 logit magnitude).
                const float qs = 0.044194173824159216f;
                v0.x *= qs; v0.y *= qs;
                v1.x *= qs; v1.y *= qs;
            }
            if (EPI == 1) {
                v0.x = fexp(v0.x); v0.y = fexp(v0.y);
                v1.x = fexp(v1.x); v1.y = fexp(v1.y);
                rs0[mi] += v0.x + v0.y;
                rs1[mi] += v1.x + v1.y;
            }
            if (EPI == 2) {
                v0.x *= il0; v0.y *= il0;
                v1.x *= il1; v1.y *= il1;
            }
            if (EPI == 3) {
                float* c0 = (float*)Cv + (size_t)b * sC + (size_t)r * ldc + col0;
                float* c1 = c0 + (size_t)8 * ldc;
                *reinterpret_cast<float2*>(c0 + c) = v0;
                *reinterpret_cast<float2*>(c1 + c) = v1;
            } else {
                __half* c0 = (__half*)Cv + (size_t)b * sC + (size_t)r * ldc + col0;
                __half* c1 = c0 + (size_t)8 * ldc;
                *reinterpret_cast<__half2*>(c0 + c) = __floats2half2_rn(v0.x, v0.y);
                *reinterpret_cast<__half2*>(c1 + c) = __floats2half2_rn(v1.x, v1.y);
            }
        }
    }

    if (EPI == 1) {
        #pragma unroll
        for (int mi = 0; mi < 4; mi++) {
            rs0[mi] += __shfl_xor_sync(0xFFFFFFFF, rs0[mi], 1);
            rs0[mi] += __shfl_xor_sync(0xFFFFFFFF, rs0[mi], 2);
            rs1[mi] += __shfl_xor_sync(0xFFFFFFFF, rs1[mi], 1);
            rs1[mi] += __shfl_xor_sync(0xFFFFFFFF, rs1[mi], 2);
        }
        if (q == 0) {
            int slot = blockIdx.x * 2 + (warp >> 1);
            size_t base = (size_t)slot * TOK + (size_t)b * SEQ + row0 + wr;
            #pragma unroll
            for (int mi = 0; mi < 4; mi++) {
                g_Lpart[base + mi * 16 + g]     = rs0[mi];
                g_Lpart[base + mi * 16 + g + 8] = rs1[mi];
            }
        }
    }
}

// ---------------- row-sum finalize: invl[r] = 1 / sum_32 Lpart ----------------
__global__ void __launch_bounds__(256) rowsum_final(
    const float* __restrict__ LP, float* __restrict__ invl)
{
    int r = blockIdx.x * 256 + threadIdx.x;
    float s = 0.0f;
    #pragma unroll
    for (int i = 0; i < 32; i++) s += LP[(size_t)i * TOK + r];
    invl[r] = 1.0f / s;
}

// ---------------- fp32 -> fp16 copy ----------------
__global__ void __launch_bounds__(256) round_h(
    const float* __restrict__ in, __half* __restrict__ out)
{
    size_t i = ((size_t)blockIdx.x * 256 + threadIdx.x) * 8;
    float4 v0 = *reinterpret_cast<const float4*>(in + i);
    float4 v1 = *reinterpret_cast<const float4*>(in + i + 4);
    __half2 h[4];
    h[0] = __floats2half2_rn(v0.x, v0.y);
    h[1] = __floats2half2_rn(v0.z, v0.w);
    h[2] = __floats2half2_rn(v1.x, v1.y);
    h[3] = __floats2half2_rn(v1.z, v1.w);
    *reinterpret_cast<uint4*>(out + i) = *reinterpret_cast<uint4*>(h);
}

// ---------------- batched 512x512 weight transpose (fp32 -> fp16) ----------
__global__ void __launch_bounds__(256) transpose_w4(
    const float* __restrict__ w0, const float* __restrict__ w1,
    const float* __restrict__ w2, const float* __restrict__ w3,
    __half* __restrict__ out)
{
    __shared__ float t[32][33];
    const float* in = (blockIdx.z == 0) ? w0 : (blockIdx.z == 1) ? w1
                     : (blockIdx.z == 2) ? w2 : w3;
    out += (size_t)blockIdx.z * EMB * EMB;
    const int x = blockIdx.x * 32 + threadIdx.x;
    const int y0 = blockIdx.y * 32;
    #pragma unroll
    for (int j = threadIdx.y; j < 32; j += 8)
        t[j][threadIdx.x] = in[(size_t)(y0 + j) * EMB + x];
    __syncthreads();
    const int ox = blockIdx.y * 32 + threadIdx.x;
    const int oy0 = blockIdx.x * 32;
    #pragma unroll
    for (int j = threadIdx.y; j < 32; j += 8)
        out[(size_t)(oy0 + j) * EMB + ox] = __float2half_rn(t[threadIdx.x][j]);
}

__global__ void __launch_bounds__(256) transpose_h2h(
    const __half* __restrict__ in, __half* __restrict__ out,
    int ldIn, int ldOut, size_t sIn, size_t sOut)
{
    __shared__ __half t[32][34];
    in  += (size_t)blockIdx.z * sIn;
    out += (size_t)blockIdx.z * sOut;
    const int x = blockIdx.x * 32 + threadIdx.x;
    const int y0 = blockIdx.y * 32;
    #pragma unroll
    for (int j = threadIdx.y; j < 32; j += 8)
        t[j][threadIdx.x] = in[(size_t)(y0 + j) * ldIn + x];
    __syncthreads();
    const int ox = blockIdx.y * 32 + threadIdx.x;
    const int oy0 = blockIdx.x * 32;
    #pragma unroll
    for (int j = threadIdx.y; j < 32; j += 8)
        out[(size_t)(oy0 + j) * ldOut + ox] = t[threadIdx.x][j];
}

// ---------------- bias concat ----------------
__global__ void __launch_bounds__(256) concat_bias(
    const float* __restrict__ a, const float* __restrict__ b,
    const float* __restrict__ c, float* __restrict__ o)
{
    int i = blockIdx.x * 256 + threadIdx.x;   // 0..1535
    float v = (i < 512) ? a[i] : ((i < 1024) ? b[i - 512] : c[i - 1024]);
    o[i] = v;
}

// ---------------- host ----------------
extern "C" void kernel_launch(void* const* d_in, const int* in_sizes, int n_in,
                              void* d_out, int out_size)
{
    const float* x  = (const float*)d_in[0];
    const float* Wq = (const float*)d_in[1];
    const float* bq = (const float*)d_in[2];
    const float* Wk = (const float*)d_in[3];
    const float* bk = (const float*)d_in[4];
    const float* Wv = (const float*)d_in[5];
    const float* bv = (const float*)d_in[6];
    const float* Wo = (const float*)d_in[7];
    const float* bo = (const float*)d_in[8];
    float* out = (float*)d_out;

    __half *Xh, *QKV, *Vt, *S, *O, *WT;
    float *Bqkv, *LP, *L;
    cudaGetSymbolAddress((void**)&Xh,   g_Xh);
    cudaGetSymbolAddress((void**)&QKV,  g_QKV);
    cudaGetSymbolAddress((void**)&Vt,   g_Vt);
    cudaGetSymbolAddress((void**)&S,    g_S);
    cudaGetSymbolAddress((void**)&O,    g_O);
    cudaGetSymbolAddress((void**)&WT,   g_WT);
    cudaGetSymbolAddress((void**)&Bqkv, g_Bqkv);
    cudaGetSymbolAddress((void**)&LP,   g_Lpart);
    cudaGetSymbolAddress((void**)&L,    g_L);

    cudaFuncSetAttribute(gemm_nt<0>, cudaFuncAttributeMaxDynamicSharedMemorySize, SMEM_BYTES);
    cudaFuncSetAttribute(gemm_nt<1>, cudaFuncAttributeMaxDynamicSharedMemorySize, SMEM_BYTES);
    cudaFuncSetAttribute(gemm_nt<2>, cudaFuncAttributeMaxDynamicSharedMemorySize, SMEM_BYTES);
    cudaFuncSetAttribute(gemm_nt<3>, cudaFuncAttributeMaxDynamicSharedMemorySize, SMEM_BYTES);

    const size_t W2 = (size_t)EMB * EMB;

    // x -> fp16
    round_h<<<(TOK * EMB) / (256 * 8), 256>>>(x, Xh);

    // All 4 weight transposes in ONE launch (fp32 -> fp16).
    dim3 tb(32, 8);
    dim3 tgW4(EMB / 32, EMB / 32, 4);
    transpose_w4<<<tgW4, tb>>>(Wq, Wk, Wv, Wo, WT);
    concat_bias<<<6, 256>>>(bq, bk, bv, Bqkv);

    // Fused QKV projection (Q columns pre-scaled by 1/sqrt(d) in epilogue)
    dim3 gqkv(3 * EMB / 128, TOK / 128, 1);
    gemm_nt<0><<<gqkv, 128, SMEM_BYTES>>>(
        Xh, WT, Bqkv, QKV, EMB, EMB, 3 * EMB, EMB, 0, 0, 0, 0, 1.0f);

    // V^T per batch: [EMB, SEQ] (V = QKV cols 1024..1535)
    dim3 tgV(EMB / 32, SEQ / 32, BATCH);
    transpose_h2h<<<tgV, tb>>>(QKV + 2 * EMB, Vt, 3 * EMB, SEQ,
                               (size_t)SEQ * 3 * EMB, (size_t)SEQ * EMB);

    // Scores (fp16 accumulate; Q pre-scaled) + fused exp + row partial sums
    dim3 gscore(SEQ / 128, SEQ / 128, BATCH);
    gemm_nt<1><<<gscore, 128, SMEM_BYTES>>>(
        QKV, QKV + EMB, nullptr, S, 3 * EMB, 3 * EMB, SEQ, EMB,
        (size_t)SEQ * 3 * EMB, (size_t)SEQ * 3 * EMB, (size_t)SEQ * SEQ, 0, 1.0f);

    // invl[r] = 1 / sum(exp row)
    rowsum_final<<<TOK / 256, 256>>>(LP, L);

    // O[b] = (S[b] @ V[b]) * invl[row] -> fp16 (fp32 accum)
    dim3 gav(EMB / 128, SEQ / 128, BATCH);
    gemm_nt<2><<<gav, 128, SMEM_BYTES>>>(
        S, Vt, L, O, SEQ, SEQ, EMB, SEQ,
        (size_t)SEQ * SEQ, (size_t)SEQ * EMB, (size_t)SEQ * EMB, SEQ, 1.0f);

    // Final projection: out = O @ Wo + bo (fp32 out, fp32 accum)
    dim3 gout(EMB / 128, TOK / 128, 1);
    gemm_nt<3><<<gout, 128, SMEM_BYTES>>>(
        O, WT + 3 * W2, bo, out, EMB, EMB, EMB, EMB, 0, 0, 0, 0, 1.0f);
}

// round 15
// speedup vs baseline: 1.0710x; 1.0652x over previous
#include <cuda_runtime.h>
#include <cuda_fp16.h>
#include <cstdint>

#define EMB 512
#define BATCH 8
#define SEQ 2048
#define TOK (BATCH * SEQ)   // 16384

// Scratch (allocation-free rule: __device__ globals)
__device__ __half g_Xh[(size_t)TOK * EMB];
__device__ __half g_QKV[(size_t)TOK * 3 * EMB];
__device__ __half g_O[(size_t)TOK * EMB];
__device__ __half g_S[(size_t)BATCH * SEQ * SEQ];
__device__ __half g_WT[4 * EMB * EMB];
__device__ float  g_Bqkv[3 * EMB];
__device__ float  g_Lpart[32 * TOK];
__device__ float  g_L[TOK];

// ---------------- PTX helpers (compute_103-safe) ----------------
__device__ __forceinline__ uint32_t smem_u32(const void* p) {
    uint32_t a;
    asm("{ .reg .u64 t; cvta.to.shared.u64 t, %1; cvt.u32.u64 %0, t; }" : "=r"(a) : "l"(p));
    return a;
}
__device__ __forceinline__ void cp16(uint32_t s, const void* g) {
    asm volatile("cp.async.cg.shared.global [%0], [%1], 16;" :: "r"(s), "l"(g));
}
#define CP_COMMIT() asm volatile("cp.async.commit_group;" ::: "memory")
#define CP_WAIT0()  asm volatile("cp.async.wait_group 0;" ::: "memory")

#define LDSM4(r0, r1, r2, r3, addr)                                            \
    asm volatile("ldmatrix.sync.aligned.m8n8.x4.shared.b16 {%0,%1,%2,%3}, [%4];" \
        : "=r"(r0), "=r"(r1), "=r"(r2), "=r"(r3) : "r"(addr))

#define LDSM4_T(r0, r1, r2, r3, addr)                                          \
    asm volatile("ldmatrix.sync.aligned.m8n8.x4.trans.shared.b16 {%0,%1,%2,%3}, [%4];" \
        : "=r"(r0), "=r"(r1), "=r"(r2), "=r"(r3) : "r"(addr))

// FMA-pipe exp (no MUFU): x ~ [-16,16], rel err ~2e-6.
__device__ __forceinline__ float fexp(float x) {
    float t = x * 1.4426950408889634f;
    float r = rintf(t);
    float f = t - r;
    float p =          1.3333558146428443e-3f;
    p = fmaf(p, f,     9.6181291076284772e-3f);
    p = fmaf(p, f,     5.5504108664821580e-2f);
    p = fmaf(p, f,     2.4022650695910071e-1f);
    p = fmaf(p, f,     6.9314718055994531e-1f);
    p = fmaf(p, f,     1.0f);
    int i = (int)r;
    return p * __int_as_float((i + 127) << 23);
}

// fp16 MMA m16n8k16, fp32 accumulate.
__device__ __forceinline__ void mma_f16(float* d, const uint32_t* a, uint32_t b0, uint32_t b1) {
    asm volatile(
        "mma.sync.aligned.m16n8k16.row.col.f32.f16.f16.f32 "
        "{%0,%1,%2,%3}, {%4,%5,%6,%7}, {%8,%9}, {%0,%1,%2,%3};"
        : "+f"(d[0]), "+f"(d[1]), "+f"(d[2]), "+f"(d[3])
        : "r"(a[0]), "r"(a[1]), "r"(a[2]), "r"(a[3]), "r"(b0), "r"(b1));
}

// ---------------- NT fp16 GEMM (ldmatrix, 64x64 warp tiles) ----------------
// C = scale * A @ B' (+epilogue). A [M,lda] halves, K-major.
// BTRANS=false: B [N,ldb] K-major (NT; non-trans LDSM, stride-72 smem).
// BTRANS=true:  B [K,ldb] N-major (NN; V's natural layout; trans LDSM,
//               stride-136 smem -> rows 272B apart, conflict-free).
// Block tile 128x128, BK=64, 4 warps (2x2), 2-stage cp.async, 2 CTAs/SM.
// EPI: 0 = +bias, ->half (QKV)   1 = exp, row-partial-sums, ->half (score)
//      2 = *invl[row], ->half (AV)   3 = +bias, ->float (final)
#define BK 64
#define STR 72
#define STRV 136
#define TILE_HALFS (128 * STR)               // 9216 (>= 64*136=8704 for BTRANS B)
#define STAGE_HALFS (2 * TILE_HALFS)         // 18432
#define SMEM_BYTES (2 * STAGE_HALFS * 2)     // 73728

template <int EPI, bool BTRANS>
__global__ void __launch_bounds__(128, 2) gemm_nt(
    const __half* __restrict__ A, const __half* __restrict__ B,
    const float* __restrict__ aux, void* __restrict__ Cv,
    int lda, int ldb, int ldc, int K,
    size_t sA, size_t sB, size_t sC, int sAux, float scale)
{
    extern __shared__ __half smem[];
    const uint32_t sbase = smem_u32(smem);

    const int tid  = threadIdx.x;
    const int lane = tid & 31;
    const int warp = tid >> 5;
    const int wr = (warp & 1) * 64;
    const int wc = (warp >> 1) * 64;

    const int b = blockIdx.z;
    A += (size_t)b * sA;
    B += (size_t)b * sB;
    if (aux) aux += (size_t)b * sAux;
    const int row0 = blockIdx.y * 128;
    const int col0 = blockIdx.x * 128;

    float acc[4][8][4];
    #pragma unroll
    for (int mi = 0; mi < 4; mi++)
        #pragma unroll
        for (int ni = 0; ni < 8; ni++)
            #pragma unroll
            for (int j = 0; j < 4; j++) acc[mi][ni][j] = 0.0f;

    const __half* gA = A + (size_t)row0 * lda;
    const __half* gB = BTRANS ? (B + col0) : (B + (size_t)col0 * ldb);

    auto fill = [&](int t, int buf) {
        uint32_t smA = sbase + (uint32_t)buf * STAGE_HALFS * 2;
        uint32_t smB = smA + TILE_HALFS * 2;
        const __half* pa = gA + t * BK;
        {   // A: 128 rows x 64 halves (128B rows)
            const int frow0 = tid >> 3;
            const int cq    = tid & 7;
            int row = frow0;
            #pragma unroll
            for (int it = 0; it < 8; it++, row += 16) {
                uint32_t off = 2u * (uint32_t)(row * STR + cq * 8);
                cp16(smA + off, pa + (size_t)row * lda + cq * 8);
            }
        }
        if (BTRANS) {
            // B: 64 k-rows x 128 halves (256B rows), stride STRV
            const __half* pb = B + (size_t)(t * BK) * ldb + col0;
            #pragma unroll
            for (int it = 0; it < 8; it++) {
                int idx = tid + it * 128;         // 0..1023
                int row = idx >> 4, cq = idx & 15;
                uint32_t off = 2u * (uint32_t)(row * STRV + cq * 8);
                cp16(smB + off, pb + (size_t)row * ldb + cq * 8);
            }
        } else {
            const __half* pb = gB + t * BK;
            const int frow0 = tid >> 3;
            const int cq    = tid & 7;
            int row = frow0;
            #pragma unroll
            for (int it = 0; it < 8; it++, row += 16) {
                uint32_t off = 2u * (uint32_t)(row * STR + cq * 8);
                cp16(smB + off, pb + (size_t)row * ldb + cq * 8);
            }
        }
    };

    const int ktiles = K / BK;
    fill(0, 0); CP_COMMIT();

    const int g = lane >> 2;
    const int q = lane & 3;
    const int l8 = lane & 7;
    const int jj = lane >> 3;

    uint32_t aOff[4];
    #pragma unroll
    for (int mi = 0; mi < 4; mi++) {
        int row = wr + mi * 16 + (jj & 1) * 8 + l8;
        aOff[mi] = 2u * (uint32_t)(row * STR + (jj >> 1) * 8);
    }
    // B fragment offsets: matrix j covers n in +(j>>1)*8, k in +(j&1)*8.
    uint32_t bOff[4];
    #pragma unroll
    for (int p = 0; p < 4; p++) {
        int nb = wc + p * 16 + (jj >> 1) * 8;
        if (BTRANS) {
            int krow = (jj & 1) * 8 + l8;
            bOff[p] = 2u * (uint32_t)(krow * STRV + nb);
        } else {
            bOff[p] = 2u * (uint32_t)((nb + l8) * STR + (jj & 1) * 8);
        }
    }

    for (int t = 0; t < ktiles; t++) {
        CP_WAIT0();
        __syncthreads();
        if (t + 1 < ktiles) { fill(t + 1, (t + 1) & 1); CP_COMMIT(); }

        const uint32_t smA = sbase + (uint32_t)(t & 1) * STAGE_HALFS * 2;
        const uint32_t smB = smA + TILE_HALFS * 2;

        #pragma unroll
        for (int ks = 0; ks < 4; ks++) {
            const uint32_t kaddA = (uint32_t)ks * 32;            // 16 halves
            const uint32_t kaddB = BTRANS ? (uint32_t)ks * STRV * 32 : (uint32_t)ks * 32;
            uint32_t a[4][4], bb[4][4];
            #pragma unroll
            for (int mi = 0; mi < 4; mi++)
                LDSM4(a[mi][0], a[mi][1], a[mi][2], a[mi][3], smA + aOff[mi] + kaddA);
            #pragma unroll
            for (int p = 0; p < 4; p++) {
                if (BTRANS) LDSM4_T(bb[p][0], bb[p][1], bb[p][2], bb[p][3], smB + bOff[p] + kaddB);
                else        LDSM4  (bb[p][0], bb[p][1], bb[p][2], bb[p][3], smB + bOff[p] + kaddB);
            }
            #pragma unroll
            for (int p = 0; p < 4; p++)
                #pragma unroll
                for (int mi = 0; mi < 4; mi++) {
                    mma_f16(acc[mi][2 * p],     a[mi], bb[p][0], bb[p][1]);
                    mma_f16(acc[mi][2 * p + 1], a[mi], bb[p][2], bb[p][3]);
                }
        }
    }

    // Epilogue
    float rs0[4], rs1[4];
    #pragma unroll
    for (int mi = 0; mi < 4; mi++) { rs0[mi] = 0.0f; rs1[mi] = 0.0f; }

    #pragma unroll
    for (int mi = 0; mi < 4; mi++) {
        int rloc = wr + mi * 16 + g;
        int r = row0 + rloc;
        float il0 = 1.0f, il1 = 1.0f;
        if (EPI == 2) { il0 = aux[r]; il1 = aux[r + 8]; }
        #pragma unroll
        for (int ni = 0; ni < 8; ni++) {
            int c = wc + ni * 8 + 2 * q;
            float2 v0, v1;
            v0.x = acc[mi][ni][0] * scale;
            v0.y = acc[mi][ni][1] * scale;
            v1.x = acc[mi][ni][2] * scale;
            v1.y = acc[mi][ni][3] * scale;
            if (EPI == 0 || EPI == 3) {
                float bx = aux[col0 + c], by = aux[col0 + c + 1];
                v0.x += bx; v0.y += by;
                v1.x += bx; v1.y += by;
            }
            if (EPI == 1) {
                v0.x = fexp(v0.x); v0.y = fexp(v0.y);
                v1.x = fexp(v1.x); v1.y = fexp(v1.y);
                rs0[mi] += v0.x + v0.y;
                rs1[mi] += v1.x + v1.y;
            }
            if (EPI == 2) {
                v0.x *= il0; v0.y *= il0;
                v1.x *= il1; v1.y *= il1;
            }
            if (EPI == 3) {
                float* c0 = (float*)Cv + (size_t)b * sC + (size_t)r * ldc + col0;
                float* c1 = c0 + (size_t)8 * ldc;
                *reinterpret_cast<float2*>(c0 + c) = v0;
                *reinterpret_cast<float2*>(c1 + c) = v1;
            } else {
                __half* c0 = (__half*)Cv + (size_t)b * sC + (size_t)r * ldc + col0;
                __half* c1 = c0 + (size_t)8 * ldc;
                *reinterpret_cast<__half2*>(c0 + c) = __floats2half2_rn(v0.x, v0.y);
                *reinterpret_cast<__half2*>(c1 + c) = __floats2half2_rn(v1.x, v1.y);
            }
        }
    }

    if (EPI == 1) {
        #pragma unroll
        for (int mi = 0; mi < 4; mi++) {
            rs0[mi] += __shfl_xor_sync(0xFFFFFFFF, rs0[mi], 1);
            rs0[mi] += __shfl_xor_sync(0xFFFFFFFF, rs0[mi], 2);
            rs1[mi] += __shfl_xor_sync(0xFFFFFFFF, rs1[mi], 1);
            rs1[mi] += __shfl_xor_sync(0xFFFFFFFF, rs1[mi], 2);
        }
        if (q == 0) {
            int slot = blockIdx.x * 2 + (warp >> 1);
            size_t base = (size_t)slot * TOK + (size_t)b * SEQ + row0 + wr;
            #pragma unroll
            for (int mi = 0; mi < 4; mi++) {
                g_Lpart[base + mi * 16 + g]     = rs0[mi];
                g_Lpart[base + mi * 16 + g + 8] = rs1[mi];
            }
        }
    }
}

// ---------------- row-sum finalize: invl[r] = 1 / sum_32 Lpart ----------------
__global__ void __launch_bounds__(256) rowsum_final(
    const float* __restrict__ LP, float* __restrict__ invl)
{
    int r = blockIdx.x * 256 + threadIdx.x;
    float s = 0.0f;
    #pragma unroll
    for (int i = 0; i < 32; i++) s += LP[(size_t)i * TOK + r];
    invl[r] = 1.0f / s;
}

// -------- fused prep: x->fp16 copy, 4 weight transposes, bias concat --------
// grid layout (flat blockIdx.x, 256 threads):
//   [0, 4096)        : round_h   (8 floats/thread)
//   [4096, 5120)     : transpose 32x32 tiles of W[z] (z = block/256)
//   [5120, 5126)     : concat_bias
__global__ void __launch_bounds__(256) prep(
    const float* __restrict__ x, __half* __restrict__ Xh,
    const float* __restrict__ w0, const float* __restrict__ w1,
    const float* __restrict__ w2, const float* __restrict__ w3,
    __half* __restrict__ WT,
    const float* __restrict__ bq, const float* __restrict__ bk,
    const float* __restrict__ bv, float* __restrict__ Bqkv)
{
    __shared__ float t[32][33];
    const int bid = blockIdx.x;
    const int tid = threadIdx.x;

    if (bid < 4096) {
        size_t i = ((size_t)bid * 256 + tid) * 8;
        float4 v0 = *reinterpret_cast<const float4*>(x + i);
        float4 v1 = *reinterpret_cast<const float4*>(x + i + 4);
        __half2 h[4];
        h[0] = __floats2half2_rn(v0.x, v0.y);
        h[1] = __floats2half2_rn(v0.z, v0.w);
        h[2] = __floats2half2_rn(v1.x, v1.y);
        h[3] = __floats2half2_rn(v1.z, v1.w);
        *reinterpret_cast<uint4*>(Xh + i) = *reinterpret_cast<uint4*>(h);
    } else if (bid < 5120) {
        int b2 = bid - 4096;
        int z = b2 >> 8;
        int rem = b2 & 255;
        int bx = rem & 15, by = rem >> 4;
        const float* in = (z == 0) ? w0 : (z == 1) ? w1 : (z == 2) ? w2 : w3;
        __half* out = WT + (size_t)z * EMB * EMB;
        const int tx = tid & 31, ty = tid >> 5;
        const int xcol = bx * 32 + tx;
        const int y0 = by * 32;
        #pragma unroll
        for (int j = ty; j < 32; j += 8)
            t[j][tx] = in[(size_t)(y0 + j) * EMB + xcol];
        __syncthreads();
        const int ox = by * 32 + tx;
        const int oy0 = bx * 32;
        #pragma unroll
        for (int j = ty; j < 32; j += 8)
            out[(size_t)(oy0 + j) * EMB + ox] = __float2half_rn(t[tx][j]);
    } else {
        int i = (bid - 5120) * 256 + tid;   // 0..1535
        float v = (i < 512) ? bq[i] : ((i < 1024) ? bk[i - 512] : bv[i - 1024]);
        Bqkv[i] = v;
    }
}

// ---------------- host ----------------
extern "C" void kernel_launch(void* const* d_in, const int* in_sizes, int n_in,
                              void* d_out, int out_size)
{
    const float* x  = (const float*)d_in[0];
    const float* Wq = (const float*)d_in[1];
    const float* bq = (const float*)d_in[2];
    const float* Wk = (const float*)d_in[3];
    const float* bk = (const float*)d_in[4];
    const float* Wv = (const float*)d_in[5];
    const float* bv = (const float*)d_in[6];
    const float* Wo = (const float*)d_in[7];
    const float* bo = (const float*)d_in[8];
    float* out = (float*)d_out;

    __half *Xh, *QKV, *S, *O, *WT;
    float *Bqkv, *LP, *L;
    cudaGetSymbolAddress((void**)&Xh,   g_Xh);
    cudaGetSymbolAddress((void**)&QKV,  g_QKV);
    cudaGetSymbolAddress((void**)&S,    g_S);
    cudaGetSymbolAddress((void**)&O,    g_O);
    cudaGetSymbolAddress((void**)&WT,   g_WT);
    cudaGetSymbolAddress((void**)&Bqkv, g_Bqkv);
    cudaGetSymbolAddress((void**)&LP,   g_Lpart);
    cudaGetSymbolAddress((void**)&L,    g_L);

    cudaFuncSetAttribute(gemm_nt<0, false>, cudaFuncAttributeMaxDynamicSharedMemorySize, SMEM_BYTES);
    cudaFuncSetAttribute(gemm_nt<1, false>, cudaFuncAttributeMaxDynamicSharedMemorySize, SMEM_BYTES);
    cudaFuncSetAttribute(gemm_nt<2, true>,  cudaFuncAttributeMaxDynamicSharedMemorySize, SMEM_BYTES);
    cudaFuncSetAttribute(gemm_nt<3, false>, cudaFuncAttributeMaxDynamicSharedMemorySize, SMEM_BYTES);

    const float scale = 0.044194173824159216f;  // 1/sqrt(512)
    const size_t W2 = (size_t)EMB * EMB;

    // Fused prep: x->fp16, weight transposes, bias concat (one launch)
    prep<<<5126, 256>>>(x, Xh, Wq, Wk, Wv, Wo, WT, bq, bk, bv, Bqkv);

    // Fused QKV projection: QKV[16384,1536] = Xh @ [Wq|Wk|Wv] + b -> fp16
    dim3 gqkv(3 * EMB / 128, TOK / 128, 1);
    gemm_nt<0, false><<<gqkv, 128, SMEM_BYTES>>>(
        Xh, WT, Bqkv, QKV, EMB, EMB, 3 * EMB, EMB, 0, 0, 0, 0, 1.0f);

    // Scores + fused exp + row partial sums: S = exp(scale * Q @ K^T) -> fp16
    dim3 gscore(SEQ / 128, SEQ / 128, BATCH);
    gemm_nt<1, false><<<gscore, 128, SMEM_BYTES>>>(
        QKV, QKV + EMB, nullptr, S, 3 * EMB, 3 * EMB, SEQ, EMB,
        (size_t)SEQ * 3 * EMB, (size_t)SEQ * 3 * EMB, (size_t)SEQ * SEQ, 0, scale);

    // invl[r] = 1 / sum(exp row)
    rowsum_final<<<TOK / 256, 256>>>(LP, L);

    // O[b] = (S[b] @ V[b]) * invl[row] -> fp16 ; V read in natural layout
    // (B = QKV cols 1024..1535, [k][n] rows, trans-LDSM)
    dim3 gav(EMB / 128, SEQ / 128, BATCH);
    gemm_nt<2, true><<<gav, 128, SMEM_BYTES>>>(
        S, QKV + 2 * EMB, L, O, SEQ, 3 * EMB, EMB, SEQ,
        (size_t)SEQ * SEQ, (size_t)SEQ * 3 * EMB, (size_t)SEQ * EMB, SEQ, 1.0f);

    // Final projection: out = O @ Wo + bo (fp32 out)
    dim3 gout(EMB / 128, TOK / 128, 1);
    gemm_nt<3, false><<<gout, 128, SMEM_BYTES>>>(
        O, WT + 3 * W2, bo, out, EMB, EMB, EMB, EMB, 0, 0, 0, 0, 1.0f);
}